// round 4
// baseline (speedup 1.0000x reference)
#include <cuda_runtime.h>

#define NN 50000
#define EE 800000

typedef unsigned long long ull;

// ---------------- device scratch (static allocations only) ----------------
__device__ float g_q[NN * 64];
__device__ float g_kv[NN * 128];     // interleaved: [n][cp*4 + {k0,k1,v0,v1}]
__device__ float g_skip[NN * 64];
__device__ float g_u[NN * 64];
__device__ float g_h[NN * 64];
__device__ float g_ea[EE * 32];      // edge_attr permuted into CSR order
__device__ float g_M[64 * 64];       // folded Wq*We for u
__device__ float g_bu[64];
__device__ int   g_rowptr[NN + 1];
__device__ int   g_cursor[NN];
__device__ int   g_srcs[EE];
__device__ int   g_eids[EE];
__device__ int   g_part[128];

// ---------------- packed f32x2 helpers (sm_103a fma.rn.f32x2) -------------
__device__ __forceinline__ ull pk2(float x, float y) {
    ull r; asm("mov.b64 %0, {%1,%2};" : "=l"(r) : "f"(x), "f"(y)); return r;
}
__device__ __forceinline__ ull dup2(float x) { return pk2(x, x); }
__device__ __forceinline__ void up2(ull a, float& x, float& y) {
    asm("mov.b64 {%0,%1}, %2;" : "=f"(x), "=f"(y) : "l"(a));
}
__device__ __forceinline__ ull fma2(ull a, ull b, ull c) {
    ull d; asm("fma.rn.f32x2 %0, %1, %2, %3;" : "=l"(d) : "l"(a), "l"(b), "l"(c)); return d;
}
__device__ __forceinline__ ull add2(ull a, ull b) {
    ull d; asm("add.rn.f32x2 %0, %1, %2;" : "=l"(d) : "l"(a), "l"(b)); return d;
}
__device__ __forceinline__ ull mul2(ull a, ull b) {
    ull d; asm("mul.rn.f32x2 %0, %1, %2;" : "=l"(d) : "l"(a), "l"(b)); return d;
}

// ---------------- CSR build ------------------------------------------------
__global__ void k_zero_rowptr() {
    int i = blockIdx.x * blockDim.x + threadIdx.x;
    if (i <= NN) g_rowptr[i] = 0;
}

__global__ void k_hist(const int* __restrict__ dst) {
    int i = blockIdx.x * blockDim.x + threadIdx.x;
    if (i < EE) atomicAdd(&g_rowptr[dst[i] + 1], 1);
}

__global__ void k_scanA() {
    __shared__ int sd[512];
    int b = blockIdx.x, t = threadIdx.x;
    int idx = b * 512 + t;
    int v = (idx <= NN) ? g_rowptr[idx] : 0;
    sd[t] = v;
    __syncthreads();
#pragma unroll
    for (int off = 1; off < 512; off <<= 1) {
        int tv = (t >= off) ? sd[t - off] : 0;
        __syncthreads();
        sd[t] += tv;
        __syncthreads();
    }
    if (idx <= NN) g_rowptr[idx] = sd[t];
    if (t == 511) g_part[b] = sd[511];
}

__global__ void k_scanC(int nb) {
    __shared__ int sp[128];
    int b = blockIdx.x, t = threadIdx.x;
    if (t < 128) sp[t] = (t < nb) ? g_part[t] : 0;
    __syncthreads();
#pragma unroll
    for (int off = 1; off < 128; off <<= 1) {
        int tv = (t < 128 && t >= off) ? sp[t - off] : 0;
        __syncthreads();
        if (t < 128) sp[t] += tv;
        __syncthreads();
    }
    int excl = (b == 0) ? 0 : sp[b - 1];
    int idx = b * 512 + t;
    if (idx <= NN) {
        int val = g_rowptr[idx] + excl;
        g_rowptr[idx] = val;
        if (idx < NN) g_cursor[idx] = val;
    }
}

__global__ void k_scatter(const int* __restrict__ src, const int* __restrict__ dst) {
    int i = blockIdx.x * blockDim.x + threadIdx.x;
    if (i < EE) {
        int d = dst[i];
        int pos = atomicAdd(&g_cursor[d], 1);
        g_srcs[pos] = src[i];
        g_eids[pos] = i;
    }
}

__global__ void k_permute_ea(const float* __restrict__ ea) {
    int idx = blockIdx.x * blockDim.x + threadIdx.x;  // over EE*8 float4s
    if (idx < EE * 8) {
        int row = idx >> 3, c4 = idx & 7;
        int e = g_eids[row];
        float4 v = ((const float4*)ea)[(long)e * 8 + c4];
        ((float4*)g_ea)[idx] = v;
    }
}

// ---------------- fold: M = per-head Wq . We  (for u = x@M + bu) ----------
__global__ void k_fold(const float* __restrict__ Wq, const float* __restrict__ bq,
                       const float* __restrict__ We, int H) {
    int idx = blockIdx.x * 256 + threadIdx.x;
    if (idx < 4096) {
        int i = idx >> 6, j = idx & 63;
        float s = 0.f;
        if (H == 2) {
            int h = j >> 5, d = j & 31;
            for (int c = 0; c < 32; c++)
                s += Wq[i * 64 + h * 32 + c] * We[d * 64 + h * 32 + c];
        } else {
            int d = j & 31;
            for (int c = 0; c < 64; c++)
                s += Wq[i * 64 + c] * We[d * 64 + c];
            s *= 0.5f;
        }
        g_M[idx] = s;
    }
    if (idx < 64) {
        int j = idx;
        float s = 0.f;
        if (H == 2) {
            int h = j >> 5, d = j & 31;
            for (int c = 0; c < 32; c++)
                s += bq[h * 32 + c] * We[d * 64 + h * 32 + c];
        } else {
            int d = j & 31;
            for (int c = 0; c < 64; c++)
                s += bq[c] * We[d * 64 + c];
            s *= 0.5f;
        }
        g_bu[j] = s;
    }
}

// ---------------- node GEMM: [N,64] x (Wq|Wk|Wv|Ws|M) -> q,kv,skip,u ------
__global__ __launch_bounds__(320, 2) void k_node_gemm5(
    const float* __restrict__ xin, int in_is_gh,
    const float* __restrict__ Wq, const float* __restrict__ bq,
    const float* __restrict__ Wk, const float* __restrict__ bk,
    const float* __restrict__ Wv, const float* __restrict__ bv,
    const float* __restrict__ Ws, const float* __restrict__ bs)
{
    __shared__ __align__(16) float xs[64 * 8];
    const float* x = in_is_gh ? g_h : xin;
    int tid = threadIdx.x;
    int sel = tid >> 6, col = tid & 63;

    const float* W; const float* B; float* O; int RS, coff;
    if      (sel == 0) { W = Wq;  B = bq;   O = g_q;    RS = 64;  coff = col; }
    else if (sel == 1) { W = Wk;  B = bk;   O = g_kv;   RS = 128; coff = (col >> 1) * 4 + (col & 1); }
    else if (sel == 2) { W = Wv;  B = bv;   O = g_kv;   RS = 128; coff = (col >> 1) * 4 + 2 + (col & 1); }
    else if (sel == 3) { W = Ws;  B = bs;   O = g_skip; RS = 64;  coff = col; }
    else               { W = g_M; B = g_bu; O = g_u;    RS = 64;  coff = col; }

    float w[64];
#pragma unroll
    for (int d = 0; d < 64; d++) w[d] = W[d * 64 + col];
    float bias = B[col];

    const int ntiles = NN / 8;  // 6250
    for (int t = blockIdx.x; t < ntiles; t += gridDim.x) {
        int n0 = t * 8;
        __syncthreads();
        for (int idx = tid; idx < 512; idx += 320) {
            int nl = idx >> 6, d = idx & 63;
            xs[d * 8 + nl] = x[(n0 + nl) * 64 + d];
        }
        __syncthreads();

        ull acc2[4];
#pragma unroll
        for (int p = 0; p < 4; p++) acc2[p] = dup2(bias);

#pragma unroll
        for (int d = 0; d < 64; d++) {
            ull wd = dup2(w[d]);
            ulonglong2 xa = *(const ulonglong2*)&xs[d * 8];
            ulonglong2 xb = *(const ulonglong2*)&xs[d * 8 + 4];
            acc2[0] = fma2(xa.x, wd, acc2[0]);
            acc2[1] = fma2(xa.y, wd, acc2[1]);
            acc2[2] = fma2(xb.x, wd, acc2[2]);
            acc2[3] = fma2(xb.y, wd, acc2[3]);
        }
#pragma unroll
        for (int p = 0; p < 4; p++) {
            float a, b; up2(acc2[p], a, b);
            O[(n0 + 2 * p) * RS + coff]     = a;
            O[(n0 + 2 * p + 1) * RS + coff] = b;
        }
    }
}

// ---------------- fused edge aggregation: warp per dst node ----------------
// Software-pipelined: loads for pair p+2, alpha-reduce for pair p+1,
// softmax-update/accumulate for pair p. kv interleaved gather (LDG.128).
template <int H>
__global__ __launch_bounds__(256, 4) void k_edge_agg(
    const float* __restrict__ We,
    float* __restrict__ out, int out_is_gh,
    const float* __restrict__ prelu, int apply_prelu)
{
    __shared__ __align__(16) float we_s[32 * 64];
    __shared__ __align__(16) float zs[8][64];

    int tid = threadIdx.x;
    int lane = tid & 31;
    int wslot = tid >> 5;
    int n = blockIdx.x * 8 + wslot;

    for (int idx = tid; idx < 2048; idx += 256) we_s[idx] = We[idx];
    __syncthreads();

    float* o = out_is_gh ? g_h : out;

    ull q2 = *(const ull*)&g_q[n * 64 + 2 * lane];
    ull u2 = *(const ull*)&g_u[n * 64 + 2 * lane];

    ull accv = 0, accz = 0;
    float m = -3.0e38f, s = 0.f;
    const float scale = (H == 2) ? 0.17677669529663687f : 0.125f;
    const int eaoff = (2 * lane) & 31;
    const int kvo = lane * 4;

    int beg = g_rowptr[n], end = g_rowptr[n + 1];
    int deg = end - beg;
    int np = deg >> 1;

#define LOADP(I, K0, K1, V0, V1, E0, E1)                                      \
    {                                                                         \
        int s0_ = g_srcs[(I)], s1_ = g_srcs[(I) + 1];                         \
        ulonglong2 kv0_ = *(const ulonglong2*)&g_kv[s0_ * 128 + kvo];         \
        ulonglong2 kv1_ = *(const ulonglong2*)&g_kv[s1_ * 128 + kvo];         \
        K0 = kv0_.x; V0 = kv0_.y; K1 = kv1_.x; V1 = kv1_.y;                   \
        E0 = *(const ull*)&g_ea[(I) * 32 + eaoff];                            \
        E1 = *(const ull*)&g_ea[((I) + 1) * 32 + eaoff];                      \
    }

#define ALPHA2(K0, K1, E0, E1, A0, A1)                                        \
    {                                                                         \
        ull pa_ = add2(mul2(q2, K0), mul2(u2, E0));                           \
        ull pb_ = add2(mul2(q2, K1), mul2(u2, E1));                           \
        float ax_, ay_, bx_, by_;                                             \
        up2(pa_, ax_, ay_); up2(pb_, bx_, by_);                               \
        float pla_ = ax_ + ay_, plb_ = bx_ + by_;                             \
        pla_ += __shfl_xor_sync(0xffffffffu, pla_, 1);                        \
        plb_ += __shfl_xor_sync(0xffffffffu, plb_, 1);                        \
        pla_ += __shfl_xor_sync(0xffffffffu, pla_, 2);                        \
        plb_ += __shfl_xor_sync(0xffffffffu, plb_, 2);                        \
        pla_ += __shfl_xor_sync(0xffffffffu, pla_, 4);                        \
        plb_ += __shfl_xor_sync(0xffffffffu, plb_, 4);                        \
        pla_ += __shfl_xor_sync(0xffffffffu, pla_, 8);                        \
        plb_ += __shfl_xor_sync(0xffffffffu, plb_, 8);                        \
        if (H == 1) {                                                         \
            pla_ += __shfl_xor_sync(0xffffffffu, pla_, 16);                   \
            plb_ += __shfl_xor_sync(0xffffffffu, plb_, 16);                   \
        }                                                                     \
        A0 = pla_ * scale; A1 = plb_ * scale;                                 \
    }

#define ACCUM2(A0, A1, V0, V1, E0, E1)                                        \
    {                                                                         \
        float nm_ = fmaxf(m, fmaxf(A0, A1));                                  \
        float sc_ = __expf(m - nm_);                                          \
        float w0_ = __expf(A0 - nm_);                                         \
        float w1_ = __expf(A1 - nm_);                                         \
        s = s * sc_ + w0_ + w1_;                                              \
        m = nm_;                                                              \
        ull sc2_ = dup2(sc_), w02_ = dup2(w0_), w12_ = dup2(w1_);             \
        accv = fma2(accv, sc2_, fma2(w02_, V0, mul2(w12_, V1)));              \
        accz = fma2(accz, sc2_, fma2(w02_, E0, mul2(w12_, E1)));              \
    }

    int tb = beg;
    if (np >= 2) {
        ull kA0, kA1, vA0, vA1, eA0, eA1;
        ull kB0, kB1, vB0, vB1, eB0, eB1;
        float aA0, aA1;
        LOADP(beg, kA0, kA1, vA0, vA1, eA0, eA1);
        LOADP(beg + 2, kB0, kB1, vB0, vB1, eB0, eB1);
        ALPHA2(kA0, kA1, eA0, eA1, aA0, aA1);
        int i = beg + 4;
#pragma unroll 2
        for (int p = 0; p < np - 2; p++) {
            ull kN0, kN1, vN0, vN1, eN0, eN1;
            LOADP(i, kN0, kN1, vN0, vN1, eN0, eN1);
            i += 2;
            float aB0, aB1;
            ALPHA2(kB0, kB1, eB0, eB1, aB0, aB1);
            ACCUM2(aA0, aA1, vA0, vA1, eA0, eA1);
            vA0 = vB0; vA1 = vB1; eA0 = eB0; eA1 = eB1; aA0 = aB0; aA1 = aB1;
            kB0 = kN0; kB1 = kN1; vB0 = vN0; vB1 = vN1; eB0 = eN0; eB1 = eN1;
        }
        float aB0, aB1;
        ALPHA2(kB0, kB1, eB0, eB1, aB0, aB1);
        ACCUM2(aA0, aA1, vA0, vA1, eA0, eA1);
        ACCUM2(aB0, aB1, vB0, vB1, eB0, eB1);
        tb = beg + 2 * np;
    }

    // scalar tail: odd edge, or whole list when deg < 4
    for (int i2 = tb; i2 < end; i2++) {
        int s0 = g_srcs[i2];
        ulonglong2 kv0 = *(const ulonglong2*)&g_kv[s0 * 128 + kvo];
        ull e0 = *(const ull*)&g_ea[i2 * 32 + eaoff];
        ull pa = add2(mul2(q2, kv0.x), mul2(u2, e0));
        float ax, ay; up2(pa, ax, ay);
        float pla = ax + ay;
        pla += __shfl_xor_sync(0xffffffffu, pla, 1);
        pla += __shfl_xor_sync(0xffffffffu, pla, 2);
        pla += __shfl_xor_sync(0xffffffffu, pla, 4);
        pla += __shfl_xor_sync(0xffffffffu, pla, 8);
        if (H == 1) pla += __shfl_xor_sync(0xffffffffu, pla, 16);
        float a0 = pla * scale;
        float nm = fmaxf(m, a0);
        float sc = __expf(m - nm);
        float w0 = __expf(a0 - nm);
        s = s * sc + w0;
        m = nm;
        accv = fma2(accv, dup2(sc), mul2(dup2(w0), kv0.y));
        accz = fma2(accz, dup2(sc), mul2(dup2(w0), e0));
    }

    // z @ We per node (epilogue)
    float zx, zy; up2(accz, zx, zy);
    zs[wslot][2 * lane] = zx;
    zs[wslot][2 * lane + 1] = zy;
    __syncwarp();

    ull ze = 0;
    int base = (H == 2) ? ((lane >> 4) * 32) : 0;
#pragma unroll
    for (int d = 0; d < 32; d++) {
        ull wp = *(const ull*)&we_s[d * 64 + 2 * lane];
        ze = fma2(dup2(zs[wslot][base + d]), wp, ze);
    }

    ull skip2 = *(const ull*)&g_skip[n * 64 + 2 * lane];
    float inv = (s > 0.f) ? 1.f / s : 0.f;
    float avx, avy; up2(accv, avx, avy);
    float ex, ey; up2(ze, ex, ey);
    float sx, sy; up2(skip2, sx, sy);
    float ox = (avx + ex) * inv + sx;
    float oy = (avy + ey) * inv + sy;
    if (apply_prelu) {
        float a = *prelu;
        ox = (ox >= 0.f) ? ox : a * ox;
        oy = (oy >= 0.f) ? oy : a * oy;
    }
    *(float2*)&o[n * 64 + 2 * lane] = make_float2(ox, oy);

#undef LOADP
#undef ALPHA2
#undef ACCUM2
}

// ---------------- launch ----------------------------------------------------
extern "C" void kernel_launch(void* const* d_in, const int* in_sizes, int n_in,
                              void* d_out, int out_size)
{
    const float* x  = (const float*)d_in[0];
    const float* ea = (const float*)d_in[1];
    const int*   ei = (const int*)d_in[2];
    const int* src = ei;
    const int* dst = ei + EE;

    const float *Wq[3], *bq[3], *Wk[3], *bk[3], *Wv[3], *bv[3], *We[3], *Ws[3], *bs[3];
    for (int l = 0; l < 3; l++) {
        int b = 3 + 9 * l;
        Wq[l] = (const float*)d_in[b + 0];
        bq[l] = (const float*)d_in[b + 1];
        Wk[l] = (const float*)d_in[b + 2];
        bk[l] = (const float*)d_in[b + 3];
        Wv[l] = (const float*)d_in[b + 4];
        bv[l] = (const float*)d_in[b + 5];
        We[l] = (const float*)d_in[b + 6];
        Ws[l] = (const float*)d_in[b + 7];
        bs[l] = (const float*)d_in[b + 8];
    }
    const float* prelu = (const float*)d_in[30];
    float* out = (float*)d_out;

    const int NB = (NN + 1 + 511) / 512;  // 98

    k_zero_rowptr<<<(NN + 256) / 256, 256>>>();
    k_hist<<<(EE + 255) / 256, 256>>>(dst);
    k_scanA<<<NB, 512>>>();
    k_scanC<<<NB, 512>>>(NB);
    k_scatter<<<(EE + 255) / 256, 256>>>(src, dst);
    k_permute_ea<<<(EE * 8 + 255) / 256, 256>>>(ea);

    const int EDGE_BLOCKS = NN / 8;  // 6250

    // layer 0 (H=2, prelu)
    k_fold<<<16, 256>>>(Wq[0], bq[0], We[0], 2);
    k_node_gemm5<<<592, 320>>>(x, 0, Wq[0], bq[0], Wk[0], bk[0], Wv[0], bv[0], Ws[0], bs[0]);
    k_edge_agg<2><<<EDGE_BLOCKS, 256>>>(We[0], nullptr, 1, prelu, 1);

    // layer 1 (H=2, prelu)
    k_fold<<<16, 256>>>(Wq[1], bq[1], We[1], 2);
    k_node_gemm5<<<592, 320>>>(nullptr, 1, Wq[1], bq[1], Wk[1], bk[1], Wv[1], bv[1], Ws[1], bs[1]);
    k_edge_agg<2><<<EDGE_BLOCKS, 256>>>(We[1], nullptr, 1, prelu, 1);

    // layer 2 (H=1, no prelu, write d_out)
    k_fold<<<16, 256>>>(Wq[2], bq[2], We[2], 1);
    k_node_gemm5<<<592, 320>>>(nullptr, 1, Wq[2], bq[2], Wk[2], bk[2], Wv[2], bv[2], Ws[2], bs[2]);
    k_edge_agg<1><<<EDGE_BLOCKS, 256>>>(We[2], out, 0, prelu, 0);
}

// round 5
// speedup vs baseline: 1.0546x; 1.0546x over previous
#include <cuda_runtime.h>

#define NN 50000
#define EE 800000

typedef unsigned long long ull;

// ---------------- device scratch (static allocations only) ----------------
__device__ float g_q[NN * 64];
__device__ float g_kv[NN * 128];     // interleaved: [n][cp*4 + {k0,k1,v0,v1}]
__device__ float g_skip[NN * 64];
__device__ float g_u[NN * 64];
__device__ float g_h[NN * 64];
__device__ float g_ea[EE * 32];      // edge_attr permuted into CSR order
__device__ float g_M[64 * 64];       // folded Wq*We for u
__device__ float g_bu[64];
__device__ int   g_rowptr[NN + 1];
__device__ int   g_cursor[NN];
__device__ int   g_srcs[EE];
__device__ int   g_eids[EE];
__device__ int   g_part[128];

// ---------------- packed f32x2 helpers (sm_103a fma.rn.f32x2) -------------
__device__ __forceinline__ ull pk2(float x, float y) {
    ull r; asm("mov.b64 %0, {%1,%2};" : "=l"(r) : "f"(x), "f"(y)); return r;
}
__device__ __forceinline__ ull dup2(float x) { return pk2(x, x); }
__device__ __forceinline__ void up2(ull a, float& x, float& y) {
    asm("mov.b64 {%0,%1}, %2;" : "=f"(x), "=f"(y) : "l"(a));
}
__device__ __forceinline__ ull fma2(ull a, ull b, ull c) {
    ull d; asm("fma.rn.f32x2 %0, %1, %2, %3;" : "=l"(d) : "l"(a), "l"(b), "l"(c)); return d;
}
__device__ __forceinline__ ull add2(ull a, ull b) {
    ull d; asm("add.rn.f32x2 %0, %1, %2;" : "=l"(d) : "l"(a), "l"(b)); return d;
}
__device__ __forceinline__ ull mul2(ull a, ull b) {
    ull d; asm("mul.rn.f32x2 %0, %1, %2;" : "=l"(d) : "l"(a), "l"(b)); return d;
}

// ---------------- CSR build ------------------------------------------------
__global__ void k_zero_rowptr() {
    int i = blockIdx.x * blockDim.x + threadIdx.x;
    if (i <= NN) g_rowptr[i] = 0;
}

__global__ void k_hist(const int* __restrict__ dst) {
    int i = blockIdx.x * blockDim.x + threadIdx.x;
    if (i < EE) atomicAdd(&g_rowptr[dst[i] + 1], 1);
}

__global__ void k_scanA() {
    __shared__ int sd[512];
    int b = blockIdx.x, t = threadIdx.x;
    int idx = b * 512 + t;
    int v = (idx <= NN) ? g_rowptr[idx] : 0;
    sd[t] = v;
    __syncthreads();
#pragma unroll
    for (int off = 1; off < 512; off <<= 1) {
        int tv = (t >= off) ? sd[t - off] : 0;
        __syncthreads();
        sd[t] += tv;
        __syncthreads();
    }
    if (idx <= NN) g_rowptr[idx] = sd[t];
    if (t == 511) g_part[b] = sd[511];
}

__global__ void k_scanC(int nb) {
    __shared__ int sp[128];
    int b = blockIdx.x, t = threadIdx.x;
    if (t < 128) sp[t] = (t < nb) ? g_part[t] : 0;
    __syncthreads();
#pragma unroll
    for (int off = 1; off < 128; off <<= 1) {
        int tv = (t < 128 && t >= off) ? sp[t - off] : 0;
        __syncthreads();
        if (t < 128) sp[t] += tv;
        __syncthreads();
    }
    int excl = (b == 0) ? 0 : sp[b - 1];
    int idx = b * 512 + t;
    if (idx <= NN) {
        int val = g_rowptr[idx] + excl;
        g_rowptr[idx] = val;
        if (idx < NN) g_cursor[idx] = val;
    }
}

__global__ void k_scatter(const int* __restrict__ src, const int* __restrict__ dst) {
    int i = blockIdx.x * blockDim.x + threadIdx.x;
    if (i < EE) {
        int d = dst[i];
        int pos = atomicAdd(&g_cursor[d], 1);
        g_srcs[pos] = src[i];
        g_eids[pos] = i;
    }
}

__global__ void k_permute_ea(const float* __restrict__ ea) {
    int idx = blockIdx.x * blockDim.x + threadIdx.x;  // over EE*8 float4s
    if (idx < EE * 8) {
        int row = idx >> 3, c4 = idx & 7;
        int e = g_eids[row];
        float4 v = ((const float4*)ea)[(long)e * 8 + c4];
        ((float4*)g_ea)[idx] = v;
    }
}

// ---------------- fold: M = per-head Wq . We  (for u = x@M + bu) ----------
__global__ void k_fold(const float* __restrict__ Wq, const float* __restrict__ bq,
                       const float* __restrict__ We, int H) {
    int idx = blockIdx.x * 256 + threadIdx.x;
    if (idx < 4096) {
        int i = idx >> 6, j = idx & 63;
        float s = 0.f;
        if (H == 2) {
            int h = j >> 5, d = j & 31;
            for (int c = 0; c < 32; c++)
                s += Wq[i * 64 + h * 32 + c] * We[d * 64 + h * 32 + c];
        } else {
            int d = j & 31;
            for (int c = 0; c < 64; c++)
                s += Wq[i * 64 + c] * We[d * 64 + c];
            s *= 0.5f;
        }
        g_M[idx] = s;
    }
    if (idx < 64) {
        int j = idx;
        float s = 0.f;
        if (H == 2) {
            int h = j >> 5, d = j & 31;
            for (int c = 0; c < 32; c++)
                s += bq[h * 32 + c] * We[d * 64 + h * 32 + c];
        } else {
            int d = j & 31;
            for (int c = 0; c < 64; c++)
                s += bq[c] * We[d * 64 + c];
            s *= 0.5f;
        }
        g_bu[j] = s;
    }
}

// ---------------- node GEMM: [N,64] x (Wq|Wk|Wv|Ws|M) -> q,kv,skip,u ------
__global__ __launch_bounds__(320, 2) void k_node_gemm5(
    const float* __restrict__ xin, int in_is_gh,
    const float* __restrict__ Wq, const float* __restrict__ bq,
    const float* __restrict__ Wk, const float* __restrict__ bk,
    const float* __restrict__ Wv, const float* __restrict__ bv,
    const float* __restrict__ Ws, const float* __restrict__ bs)
{
    __shared__ __align__(16) float xs[64 * 8];
    const float* x = in_is_gh ? g_h : xin;
    int tid = threadIdx.x;
    int sel = tid >> 6, col = tid & 63;

    const float* W; const float* B; float* O; int RS, coff;
    if      (sel == 0) { W = Wq;  B = bq;   O = g_q;    RS = 64;  coff = col; }
    else if (sel == 1) { W = Wk;  B = bk;   O = g_kv;   RS = 128; coff = (col >> 1) * 4 + (col & 1); }
    else if (sel == 2) { W = Wv;  B = bv;   O = g_kv;   RS = 128; coff = (col >> 1) * 4 + 2 + (col & 1); }
    else if (sel == 3) { W = Ws;  B = bs;   O = g_skip; RS = 64;  coff = col; }
    else               { W = g_M; B = g_bu; O = g_u;    RS = 64;  coff = col; }

    float w[64];
#pragma unroll
    for (int d = 0; d < 64; d++) w[d] = W[d * 64 + col];
    float bias = B[col];

    const int ntiles = NN / 8;  // 6250
    for (int t = blockIdx.x; t < ntiles; t += gridDim.x) {
        int n0 = t * 8;
        __syncthreads();
        for (int idx = tid; idx < 512; idx += 320) {
            int nl = idx >> 6, d = idx & 63;
            xs[d * 8 + nl] = x[(n0 + nl) * 64 + d];
        }
        __syncthreads();

        ull acc2[4];
#pragma unroll
        for (int p = 0; p < 4; p++) acc2[p] = dup2(bias);

#pragma unroll
        for (int d = 0; d < 64; d++) {
            ull wd = dup2(w[d]);
            ulonglong2 xa = *(const ulonglong2*)&xs[d * 8];
            ulonglong2 xb = *(const ulonglong2*)&xs[d * 8 + 4];
            acc2[0] = fma2(xa.x, wd, acc2[0]);
            acc2[1] = fma2(xa.y, wd, acc2[1]);
            acc2[2] = fma2(xb.x, wd, acc2[2]);
            acc2[3] = fma2(xb.y, wd, acc2[3]);
        }
#pragma unroll
        for (int p = 0; p < 4; p++) {
            float a, b; up2(acc2[p], a, b);
            O[(n0 + 2 * p) * RS + coff]     = a;
            O[(n0 + 2 * p + 1) * RS + coff] = b;
        }
    }
}

// ---------------- fused edge aggregation: warp per dst node ----------------
// Plain-exp softmax (no online max — alphas are O(1), exp is fp32-safe and
// the normalized ratio is identical). Loop-carried deps are only the two
// 4-cycle fma accumulator chains. 2 edges/iter, prefetch next pair.
template <int H>
__global__ __launch_bounds__(256, 4) void k_edge_agg(
    const float* __restrict__ We,
    float* __restrict__ out, int out_is_gh,
    const float* __restrict__ prelu, int apply_prelu)
{
    __shared__ __align__(16) float we_s[32 * 64];
    __shared__ __align__(16) float zs[8][64];

    int tid = threadIdx.x;
    int lane = tid & 31;
    int wslot = tid >> 5;
    int n = blockIdx.x * 8 + wslot;

    for (int idx = tid; idx < 2048; idx += 256) we_s[idx] = We[idx];
    __syncthreads();

    float* o = out_is_gh ? g_h : out;

    ull q2 = *(const ull*)&g_q[n * 64 + 2 * lane];
    ull u2 = *(const ull*)&g_u[n * 64 + 2 * lane];

    ull accv = 0, accz = 0;
    float s = 0.f;
    const float scale = (H == 2) ? 0.17677669529663687f : 0.125f;
    const int eaoff = (2 * lane) & 31;
    const int kvo = lane * 4;

    int beg = g_rowptr[n], end = g_rowptr[n + 1];
    int deg = end - beg;
    int npair = deg >> 1;
    int odd = deg & 1;

    ull k0 = 0, v0 = 0, e0 = 0, k1 = 0, v1 = 0, e1 = 0;

    if (npair > 0) {
        int s0 = g_srcs[beg], s1 = g_srcs[beg + 1];
        ulonglong2 kv0 = *(const ulonglong2*)&g_kv[s0 * 128 + kvo];
        ulonglong2 kv1 = *(const ulonglong2*)&g_kv[s1 * 128 + kvo];
        k0 = kv0.x; v0 = kv0.y; k1 = kv1.x; v1 = kv1.y;
        e0 = *(const ull*)&g_ea[beg * 32 + eaoff];
        e1 = *(const ull*)&g_ea[(beg + 1) * 32 + eaoff];
    } else if (odd) {
        int s0 = g_srcs[beg];
        ulonglong2 kv0 = *(const ulonglong2*)&g_kv[s0 * 128 + kvo];
        k0 = kv0.x; v0 = kv0.y;
        e0 = *(const ull*)&g_ea[beg * 32 + eaoff];
    }

    int i = beg;
    for (int p = 0; p < npair; p++) {
        ull ka = k0, va = v0, ea0 = e0;
        ull kb = k1, vb = v1, eb = e1;
        int j = i + 2;
        // prefetch next pair (or the odd tail edge)
        if (p + 1 < npair) {
            int s0 = g_srcs[j], s1 = g_srcs[j + 1];
            ulonglong2 kv0 = *(const ulonglong2*)&g_kv[s0 * 128 + kvo];
            ulonglong2 kv1 = *(const ulonglong2*)&g_kv[s1 * 128 + kvo];
            k0 = kv0.x; v0 = kv0.y; k1 = kv1.x; v1 = kv1.y;
            e0 = *(const ull*)&g_ea[j * 32 + eaoff];
            e1 = *(const ull*)&g_ea[(j + 1) * 32 + eaoff];
        } else if (odd) {
            int s0 = g_srcs[j];
            ulonglong2 kv0 = *(const ulonglong2*)&g_kv[s0 * 128 + kvo];
            k0 = kv0.x; v0 = kv0.y;
            e0 = *(const ull*)&g_ea[j * 32 + eaoff];
        }

        ull pa = add2(mul2(q2, ka), mul2(u2, ea0));
        ull pb = add2(mul2(q2, kb), mul2(u2, eb));
        float ax0, ay0, bx0, by0;
        up2(pa, ax0, ay0);
        up2(pb, bx0, by0);
        float pla = ax0 + ay0;
        float plb = bx0 + by0;
        pla += __shfl_xor_sync(0xffffffffu, pla, 1);
        plb += __shfl_xor_sync(0xffffffffu, plb, 1);
        pla += __shfl_xor_sync(0xffffffffu, pla, 2);
        plb += __shfl_xor_sync(0xffffffffu, plb, 2);
        pla += __shfl_xor_sync(0xffffffffu, pla, 4);
        plb += __shfl_xor_sync(0xffffffffu, plb, 4);
        pla += __shfl_xor_sync(0xffffffffu, pla, 8);
        plb += __shfl_xor_sync(0xffffffffu, plb, 8);
        if (H == 1) {
            pla += __shfl_xor_sync(0xffffffffu, pla, 16);
            plb += __shfl_xor_sync(0xffffffffu, plb, 16);
        }

        float w0 = __expf(pla * scale);
        float w1 = __expf(plb * scale);
        s += w0 + w1;

        ull w02 = dup2(w0), w12 = dup2(w1);
        accv = add2(accv, fma2(w02, va, mul2(w12, vb)));
        accz = add2(accz, fma2(w02, ea0, mul2(w12, eb)));
        i = j;
    }

    if (odd) {
        ull pa = add2(mul2(q2, k0), mul2(u2, e0));
        float ax0, ay0; up2(pa, ax0, ay0);
        float pla = ax0 + ay0;
        pla += __shfl_xor_sync(0xffffffffu, pla, 1);
        pla += __shfl_xor_sync(0xffffffffu, pla, 2);
        pla += __shfl_xor_sync(0xffffffffu, pla, 4);
        pla += __shfl_xor_sync(0xffffffffu, pla, 8);
        if (H == 1) pla += __shfl_xor_sync(0xffffffffu, pla, 16);
        float w0 = __expf(pla * scale);
        s += w0;
        ull w02 = dup2(w0);
        accv = fma2(w02, v0, accv);
        accz = fma2(w02, e0, accz);
    }

    // z @ We per node (epilogue)
    float zx, zy; up2(accz, zx, zy);
    zs[wslot][2 * lane] = zx;
    zs[wslot][2 * lane + 1] = zy;
    __syncwarp();

    ull ze = 0;
    int base = (H == 2) ? ((lane >> 4) * 32) : 0;
#pragma unroll
    for (int d = 0; d < 32; d++) {
        ull wp = *(const ull*)&we_s[d * 64 + 2 * lane];
        ze = fma2(dup2(zs[wslot][base + d]), wp, ze);
    }

    ull skip2 = *(const ull*)&g_skip[n * 64 + 2 * lane];
    float inv = (s > 0.f) ? 1.f / s : 0.f;
    float avx, avy; up2(accv, avx, avy);
    float ex, ey; up2(ze, ex, ey);
    float sx, sy; up2(skip2, sx, sy);
    float ox = (avx + ex) * inv + sx;
    float oy = (avy + ey) * inv + sy;
    if (apply_prelu) {
        float a = *prelu;
        ox = (ox >= 0.f) ? ox : a * ox;
        oy = (oy >= 0.f) ? oy : a * oy;
    }
    *(float2*)&o[n * 64 + 2 * lane] = make_float2(ox, oy);
}

// ---------------- launch ----------------------------------------------------
extern "C" void kernel_launch(void* const* d_in, const int* in_sizes, int n_in,
                              void* d_out, int out_size)
{
    const float* x  = (const float*)d_in[0];
    const float* ea = (const float*)d_in[1];
    const int*   ei = (const int*)d_in[2];
    const int* src = ei;
    const int* dst = ei + EE;

    const float *Wq[3], *bq[3], *Wk[3], *bk[3], *Wv[3], *bv[3], *We[3], *Ws[3], *bs[3];
    for (int l = 0; l < 3; l++) {
        int b = 3 + 9 * l;
        Wq[l] = (const float*)d_in[b + 0];
        bq[l] = (const float*)d_in[b + 1];
        Wk[l] = (const float*)d_in[b + 2];
        bk[l] = (const float*)d_in[b + 3];
        Wv[l] = (const float*)d_in[b + 4];
        bv[l] = (const float*)d_in[b + 5];
        We[l] = (const float*)d_in[b + 6];
        Ws[l] = (const float*)d_in[b + 7];
        bs[l] = (const float*)d_in[b + 8];
    }
    const float* prelu = (const float*)d_in[30];
    float* out = (float*)d_out;

    const int NB = (NN + 1 + 511) / 512;  // 98

    k_zero_rowptr<<<(NN + 256) / 256, 256>>>();
    k_hist<<<(EE + 255) / 256, 256>>>(dst);
    k_scanA<<<NB, 512>>>();
    k_scanC<<<NB, 512>>>(NB);
    k_scatter<<<(EE + 255) / 256, 256>>>(src, dst);
    k_permute_ea<<<(EE * 8 + 255) / 256, 256>>>(ea);

    const int EDGE_BLOCKS = NN / 8;  // 6250

    // layer 0 (H=2, prelu)
    k_fold<<<16, 256>>>(Wq[0], bq[0], We[0], 2);
    k_node_gemm5<<<592, 320>>>(x, 0, Wq[0], bq[0], Wk[0], bk[0], Wv[0], bv[0], Ws[0], bs[0]);
    k_edge_agg<2><<<EDGE_BLOCKS, 256>>>(We[0], nullptr, 1, prelu, 1);

    // layer 1 (H=2, prelu)
    k_fold<<<16, 256>>>(Wq[1], bq[1], We[1], 2);
    k_node_gemm5<<<592, 320>>>(nullptr, 1, Wq[1], bq[1], Wk[1], bk[1], Wv[1], bv[1], Ws[1], bs[1]);
    k_edge_agg<2><<<EDGE_BLOCKS, 256>>>(We[1], nullptr, 1, prelu, 1);

    // layer 2 (H=1, no prelu, write d_out)
    k_fold<<<16, 256>>>(Wq[2], bq[2], We[2], 1);
    k_node_gemm5<<<592, 320>>>(nullptr, 1, Wq[2], bq[2], Wk[2], bk[2], Wv[2], bv[2], Ws[2], bs[2]);
    k_edge_agg<1><<<EDGE_BLOCKS, 256>>>(We[2], out, 0, prelu, 0);
}